// round 14
// baseline (speedup 1.0000x reference)
#include <cuda_runtime.h>
#include <cuda_fp16.h>
#include <cuda.h>
#include <cstdint>

// LatentMap, R14: TMA tile::gather4 offload, alignment-fixed.
//
// R13 faulted: TMA smem destinations must be 128B-aligned (QSTRIDE was 288).
// Now QSTRIDE=256 (gather4 deposits 4x64B contiguous), buffers align(128).
// Readback bank conflicts from the 256B stride are eliminated by row-
// staggered reads: lane (sub,f) reads row (j+sub)&3 at step j -> every bank
// hit exactly 2x per LDS.64 (crossbar minimum). Weight component selected
// dynamically per step (sum is order-invariant re-pairing of the same FMAs).
//
// Kernel 0: embeddings f32 -> fp16 (64B rows) in __device__ scratch.
// Kernel 1: phase 1 = R12 proven scalar phase; phase 2 = double-buffered
//   4-query stages, owning lanes issue 1 gather4 each (4 rows x 64B), warp
//   blends from smem. Moves 4 gather wf/query off l1tex onto the idle TMA pipe.
// Fallback: R12-equivalent LDG kernel if tensormap encode fails.

#define IMG 1024
#define EMB 32
#define N_PTS_MAX 100000
#define WPB 8
#define QPW 32
#define STAGE_Q 4
#define NSTAGE (QPW / STAGE_Q)            // 8
#define QSTRIDE 256                       // 4 rows x 64B, contiguous TMA deposit
#define STAGE_BYTES (STAGE_Q * QSTRIDE)   // 1024
#define TX_BYTES (STAGE_Q * 4 * EMB * 2)  // 1024

__device__ __align__(128) __half g_emb[N_PTS_MAX * EMB];

// ---------------------------------------------------------------- convert
__global__ void __launch_bounds__(256) convert_kernel(
    const float* __restrict__ embeddings, int n_elems)
{
    const int i = (blockIdx.x * blockDim.x + threadIdx.x) * 4;
    if (i + 3 < n_elems) {
        const float4 v = *(const float4*)&embeddings[i];
        __half2 lo = __floats2half2_rn(v.x, v.y);
        __half2 hi = __floats2half2_rn(v.z, v.w);
        uint2 packed;
        packed.x = *(unsigned int*)&lo;
        packed.y = *(unsigned int*)&hi;
        *(uint2*)&g_emb[i] = packed;
    } else {
        for (int k = i; k < n_elems; ++k)
            g_emb[k] = __float2half_rn(embeddings[k]);
    }
}

// ---------------------------------------------------------------- helpers
__device__ __forceinline__ uint32_t smem_u32(const void* p) {
    return (uint32_t)__cvta_generic_to_shared(p);
}
__device__ __forceinline__ void mbar_init(uint32_t mbar, uint32_t count) {
    asm volatile("mbarrier.init.shared.b64 [%0], %1;" :: "r"(mbar), "r"(count) : "memory");
}
__device__ __forceinline__ void mbar_expect_tx(uint32_t mbar, uint32_t bytes) {
    asm volatile("mbarrier.arrive.expect_tx.shared.b64 _, [%0], %1;"
                 :: "r"(mbar), "r"(bytes) : "memory");
}
__device__ __forceinline__ void mbar_wait(uint32_t mbar, uint32_t parity) {
    uint32_t done;
    asm volatile(
        "{\n\t.reg .pred p;\n\t"
        "mbarrier.try_wait.parity.acquire.cta.shared::cta.b64 p, [%1], %2;\n\t"
        "selp.b32 %0, 1, 0, p;\n\t}"
        : "=r"(done) : "r"(mbar), "r"(parity) : "memory");
    if (!done) {
        asm volatile(
            "{\n\t.reg .pred P1;\n\t"
            "WAIT_LOOP_%=:\n\t"
            "mbarrier.try_wait.parity.acquire.cta.shared::cta.b64 P1, [%0], %1, 0x989680;\n\t"
            "@P1 bra.uni WAIT_DONE_%=;\n\t"
            "bra.uni WAIT_LOOP_%=;\n\t"
            "WAIT_DONE_%=:\n\t}"
            :: "r"(mbar), "r"(parity) : "memory");
    }
}
__device__ __forceinline__ void tma_gather4(uint32_t dst_smem, const CUtensorMap* tmap,
                                            int x0, int4 rows, uint32_t mbar) {
    asm volatile(
        "cp.async.bulk.tensor.2d.tile::gather4.shared::cta.global.mbarrier::complete_tx::bytes"
        " [%0], [%1, {%2, %3, %4, %5, %6}], [%7];"
        :: "r"(dst_smem), "l"(tmap), "r"(x0),
           "r"(rows.x), "r"(rows.y), "r"(rows.z), "r"(rows.w), "r"(mbar)
        : "memory");
}
__device__ __forceinline__ float4 half4_to_float4(uint2 raw) {
    const __half2 lo = *(const __half2*)&raw.x;
    const __half2 hi = *(const __half2*)&raw.y;
    const float2 a = __half22float2(lo);
    const float2 b = __half22float2(hi);
    return make_float4(a.x, a.y, b.x, b.y);
}

// ---------------------------------------------------------------- main (TMA)
__global__ void __launch_bounds__(WPB * 32, 8) latent_map_tma(
    const float2* __restrict__ position,
    const float2* __restrict__ positions,
    const int4*   __restrict__ neighbor_map,
    const float*  __restrict__ harmonics,
    float*        __restrict__ out,
    int n_q,
    const __grid_constant__ CUtensorMap tmap)
{
    __shared__ __align__(128) unsigned char s_tbuf[WPB][2][STAGE_BYTES];
    __shared__ float4   s_w [WPB][QPW];
    __shared__ int4     s_nb[WPB][QPW];
    __shared__ __align__(8) unsigned long long s_mbar[WPB][2];

    const int warp = threadIdx.x >> 5;
    const int lane = threadIdx.x & 31;
    const int qbase = (blockIdx.x * WPB + warp) * QPW;
    const bool full_tile = (qbase + QPW) <= n_q;

    const uint32_t mb0 = smem_u32(&s_mbar[warp][0]);
    const uint32_t mb1 = smem_u32(&s_mbar[warp][1]);
    const uint32_t buf0 = smem_u32(&s_tbuf[warp][0][0]);
    const uint32_t buf1 = smem_u32(&s_tbuf[warp][1][0]);

    if (lane == 0) {
        mbar_init(mb0, 1);
        mbar_init(mb1, 1);
        asm volatile("fence.proxy.async.shared::cta;" ::: "memory");
    }
    __syncwarp();

    // ---- Phase 1 (R12, proven): one query per lane ----
    int4 r_nb = make_int4(0, 0, 0, 0);
    {
        const int q = qbase + lane;
        if (full_tile || q < n_q) {
            const float2 p = position[q];
            const int ix = (int)floorf(p.x);
            const int iy = (int)floorf(p.y);
            const int4 nb = neighbor_map[ix * IMG + iy];

            const float2 p0 = positions[nb.x];
            const float2 p1 = positions[nb.y];
            const float2 p2 = positions[nb.z];
            const float2 p3 = positions[nb.w];

            const float fx = (float)ix, fy = (float)iy;
            float dx, dy;
            dx = p0.x - fx; dy = p0.y - fy;
            const float d0 = sqrtf(dx * dx + dy * dy);
            dx = p1.x - fx; dy = p1.y - fy;
            const float d1 = sqrtf(dx * dx + dy * dy);
            dx = p2.x - fx; dy = p2.y - fy;
            const float d2 = sqrtf(dx * dx + dy * dy);
            dx = p3.x - fx; dy = p3.y - fy;
            const float d3 = sqrtf(dx * dx + dy * dy);

            const float rs = 1.0f / (d0 + d1 + d2 + d3 + 1e-8f);
            float4 w;
            w.x = 1.0f - d0 * rs;
            w.y = 1.0f - d1 * rs;
            w.z = 1.0f - d2 * rs;
            w.w = 1.0f - d3 * rs;

            r_nb = nb;
            s_w [warp][lane] = w;
            s_nb[warp][lane] = nb;
        }
    }
    __syncwarp();

    const int sub = lane >> 3;        // stage-local query 0..3
    const int f   = lane & 7;         // feature quad index
    const int fq  = f * 4;
    const float4 h4 = *(const float4*)&harmonics[fq];

    if (full_tile) {
        // Prologue: stage 0 (queries 0..3, owned by lanes 0..3).
        if ((lane >> 2) == 0) {
            if ((lane & 3) == 0) mbar_expect_tx(mb0, TX_BYTES);
            tma_gather4(buf0 + (lane & 3) * QSTRIDE, &tmap, 0, r_nb, mb0);
        }

        #pragma unroll
        for (int s = 0; s < NSTAGE; ++s) {
            if (s + 1 < NSTAGE) {
                const int g = s + 1;
                const uint32_t mb = (g & 1) ? mb1 : mb0;
                const uint32_t bf = (g & 1) ? buf1 : buf0;
                if ((lane >> 2) == g) {
                    if ((lane & 3) == 0) mbar_expect_tx(mb, TX_BYTES);
                    tma_gather4(bf + (lane & 3) * QSTRIDE, &tmap, 0, r_nb, mb);
                }
            }
            mbar_wait((s & 1) ? mb1 : mb0, (s >> 1) & 1);

            // Blend: row-staggered reads, all 32 banks hit exactly 2x per LDS.
            const uint32_t base = ((s & 1) ? buf1 : buf0) + sub * QSTRIDE + f * 8;
            const float4 w = s_w[warp][s * STAGE_Q + sub];

            float4 acc = make_float4(0.f, 0.f, 0.f, 0.f);
            #pragma unroll
            for (int j = 0; j < 4; ++j) {
                const int r = (j + sub) & 3;                  // staggered row
                uint2 raw;
                asm volatile("ld.shared.v2.u32 {%0, %1}, [%2];"
                             : "=r"(raw.x), "=r"(raw.y) : "r"(base + r * 64));
                const float4 e = half4_to_float4(raw);
                const float wr = (r == 0) ? w.x : (r == 1) ? w.y : (r == 2) ? w.z : w.w;
                acc.x += wr * e.x;
                acc.y += wr * e.y;
                acc.z += wr * e.z;
                acc.w += wr * e.w;
            }
            acc.x *= h4.x; acc.y *= h4.y; acc.z *= h4.z; acc.w *= h4.w;

            *(float4*)&out[(long)(qbase + s * STAGE_Q + sub) * EMB + fq] = acc;
        }
    } else {
        // Tail path (never taken for N_Q = 1<<20): direct LDG from g_emb.
        #pragma unroll
        for (int i = 0; i < QPW; i += 4) {
            const int q = qbase + i + sub;
            if (q < n_q) {
                const int4   nb = s_nb[warp][i + sub];
                const float4 w  = s_w [warp][i + sub];
                const float4 e0 = half4_to_float4(*(const uint2*)&g_emb[(long)nb.x * EMB + fq]);
                const float4 e1 = half4_to_float4(*(const uint2*)&g_emb[(long)nb.y * EMB + fq]);
                const float4 e2 = half4_to_float4(*(const uint2*)&g_emb[(long)nb.z * EMB + fq]);
                const float4 e3 = half4_to_float4(*(const uint2*)&g_emb[(long)nb.w * EMB + fq]);
                float4 acc;
                acc.x = w.x * e0.x + w.y * e1.x + w.z * e2.x + w.w * e3.x;
                acc.y = w.x * e0.y + w.y * e1.y + w.z * e2.y + w.w * e3.y;
                acc.z = w.x * e0.z + w.y * e1.z + w.z * e2.z + w.w * e3.z;
                acc.w = w.x * e0.w + w.y * e1.w + w.z * e2.w + w.w * e3.w;
                acc.x *= h4.x; acc.y *= h4.y; acc.z *= h4.z; acc.w *= h4.w;
                *(float4*)&out[(long)q * EMB + fq] = acc;
            }
        }
    }
}

// ---------------------------------------------------------------- main (LDG fallback = R12)
__global__ void __launch_bounds__(WPB * 32, 8) latent_map_ldg(
    const float2* __restrict__ position,
    const float2* __restrict__ positions,
    const int4*   __restrict__ neighbor_map,
    const float*  __restrict__ harmonics,
    float*        __restrict__ out,
    int n_q)
{
    __shared__ int4   s_nb[WPB][QPW];
    __shared__ float4 s_w [WPB][QPW];

    const int warp = threadIdx.x >> 5;
    const int lane = threadIdx.x & 31;
    const int qbase = (blockIdx.x * WPB + warp) * QPW;
    const bool full_tile = (qbase + QPW) <= n_q;

    {
        const int q = qbase + lane;
        if (full_tile || q < n_q) {
            const float2 p = position[q];
            const int ix = (int)floorf(p.x);
            const int iy = (int)floorf(p.y);
            const int4 nb = neighbor_map[ix * IMG + iy];
            const float2 p0 = positions[nb.x];
            const float2 p1 = positions[nb.y];
            const float2 p2 = positions[nb.z];
            const float2 p3 = positions[nb.w];
            const float fx = (float)ix, fy = (float)iy;
            float dx, dy;
            dx = p0.x - fx; dy = p0.y - fy; const float d0 = sqrtf(dx*dx + dy*dy);
            dx = p1.x - fx; dy = p1.y - fy; const float d1 = sqrtf(dx*dx + dy*dy);
            dx = p2.x - fx; dy = p2.y - fy; const float d2 = sqrtf(dx*dx + dy*dy);
            dx = p3.x - fx; dy = p3.y - fy; const float d3 = sqrtf(dx*dx + dy*dy);
            const float rs = 1.0f / (d0 + d1 + d2 + d3 + 1e-8f);
            float4 w;
            w.x = 1.0f - d0 * rs; w.y = 1.0f - d1 * rs;
            w.z = 1.0f - d2 * rs; w.w = 1.0f - d3 * rs;
            s_nb[warp][lane] = nb;
            s_w [warp][lane] = w;
        }
    }
    __syncwarp();

    const int sub = lane >> 3;
    const int fq  = (lane & 7) * 4;
    const float4 h4 = *(const float4*)&harmonics[fq];

    #pragma unroll
    for (int i = 0; i < QPW; i += 4) {
        const int q = qbase + i + sub;
        if (full_tile || q < n_q) {
            const int4   nb = s_nb[warp][i + sub];
            const float4 w  = s_w [warp][i + sub];
            const float4 e0 = half4_to_float4(*(const uint2*)&g_emb[(long)nb.x * EMB + fq]);
            const float4 e1 = half4_to_float4(*(const uint2*)&g_emb[(long)nb.y * EMB + fq]);
            const float4 e2 = half4_to_float4(*(const uint2*)&g_emb[(long)nb.z * EMB + fq]);
            const float4 e3 = half4_to_float4(*(const uint2*)&g_emb[(long)nb.w * EMB + fq]);
            float4 acc;
            acc.x = w.x * e0.x + w.y * e1.x + w.z * e2.x + w.w * e3.x;
            acc.y = w.x * e0.y + w.y * e1.y + w.z * e2.y + w.w * e3.y;
            acc.z = w.x * e0.z + w.y * e1.z + w.z * e2.z + w.w * e3.z;
            acc.w = w.x * e0.w + w.y * e1.w + w.z * e2.w + w.w * e3.w;
            acc.x *= h4.x; acc.y *= h4.y; acc.z *= h4.z; acc.w *= h4.w;
            *(float4*)&out[(long)q * EMB + fq] = acc;
        }
    }
}

// ---------------------------------------------------------------- host
typedef CUresult (*PFN_tmapEncode)(
    CUtensorMap*, CUtensorMapDataType, cuuint32_t, void*,
    const cuuint64_t*, const cuuint64_t*, const cuuint32_t*, const cuuint32_t*,
    CUtensorMapInterleave, CUtensorMapSwizzle, CUtensorMapL2promotion,
    CUtensorMapFloatOOBfill);

extern "C" void kernel_launch(void* const* d_in, const int* in_sizes, int n_in,
                              void* d_out, int out_size)
{
    const float2* position     = (const float2*)d_in[0];
    const float2* positions    = (const float2*)d_in[1];
    const int4*   neighbor_map = (const int4*)d_in[2];
    const float*  embeddings   = (const float*)d_in[3];
    const float*  harmonics    = (const float*)d_in[4];
    float*        out          = (float*)d_out;

    const int n_q = in_sizes[0] / 2;
    int n_emb = in_sizes[3];
    if (n_emb > N_PTS_MAX * EMB) n_emb = N_PTS_MAX * EMB;
    const int n_pts = n_emb / EMB;

    // Kernel 0: stage embeddings as fp16.
    {
        const int block = 256;
        const int grid = (n_emb / 4 + block - 1) / block;
        convert_kernel<<<grid, block>>>(embeddings, n_emb);
    }

    // Build tensormap for g_emb [n_pts][32] fp16, 64B rows.
    bool tma_ok = false;
    CUtensorMap tmap;
    {
        void* fn = nullptr;
        cudaDriverEntryPointQueryResult qr = cudaDriverEntryPointSymbolNotFound;
#if CUDART_VERSION >= 12050
        cudaGetDriverEntryPointByVersion("cuTensorMapEncodeTiled", &fn, 12000,
                                         cudaEnableDefault, &qr);
#else
        cudaGetDriverEntryPoint("cuTensorMapEncodeTiled", &fn,
                                cudaEnableDefault, &qr);
#endif
        void* emb_dev = nullptr;
        cudaGetSymbolAddress(&emb_dev, g_emb);

        if (fn && emb_dev && qr == cudaDriverEntryPointSuccess) {
            PFN_tmapEncode encode = (PFN_tmapEncode)fn;
            cuuint64_t dims[2]    = {(cuuint64_t)EMB, (cuuint64_t)n_pts};
            cuuint64_t strides[1] = {EMB * sizeof(__half)};  // 64B row stride
            cuuint32_t box[2]     = {EMB, 1};
            cuuint32_t estr[2]    = {1, 1};
            CUresult r = encode(&tmap, CU_TENSOR_MAP_DATA_TYPE_FLOAT16, 2, emb_dev,
                                dims, strides, box, estr,
                                CU_TENSOR_MAP_INTERLEAVE_NONE,
                                CU_TENSOR_MAP_SWIZZLE_NONE,
                                CU_TENSOR_MAP_L2_PROMOTION_L2_128B,
                                CU_TENSOR_MAP_FLOAT_OOB_FILL_NONE);
            tma_ok = (r == CUDA_SUCCESS);
        }
    }

    const int queries_per_block = WPB * QPW;  // 256
    const int grid = (n_q + queries_per_block - 1) / queries_per_block;
    if (tma_ok) {
        latent_map_tma<<<grid, WPB * 32>>>(
            position, positions, neighbor_map, harmonics, out, n_q, tmap);
    } else {
        latent_map_ldg<<<grid, WPB * 32>>>(
            position, positions, neighbor_map, harmonics, out, n_q);
    }
}

// round 15
// speedup vs baseline: 1.7030x; 1.7030x over previous
#include <cuda_runtime.h>
#include <cuda_bf16.h>

// LatentMap, R15: R6 two-phase warp-cooperative kernel made PERSISTENT.
//
// R6 launched 4096 CTAs over 1184 concurrent slots = 3.46 waves; the 46%-
// full tail wave idles half the chip for ~1/3 of the runtime, matching the
// gap between the measured 65.8us and the ~58us wavefront-cycle model.
// R15 launches exactly 148 SMs x 8 CTAs = 1184 CTAs; each warp grid-strides
// over query tiles with the identical R6 inner code (phase 1: lane-per-query
// scalars -> smem; phase 2: 4 queries/iter, lane -> (sub, feature-quad),
// coalesced LDG.128 gathers + STG.128).

#define IMG 1024
#define EMB 32
#define WARPS_PER_BLOCK 8
#define QUERIES_PER_WARP 32
#define NUM_SMS 148
#define BLOCKS (NUM_SMS * 8)                 // 1184 persistent CTAs
#define TOTAL_WARPS (BLOCKS * WARPS_PER_BLOCK)  // 9472

__global__ void __launch_bounds__(WARPS_PER_BLOCK * 32, 8) latent_map_kernel(
    const float2* __restrict__ position,      // [N_Q]
    const float2* __restrict__ positions,     // [N_PTS]
    const int4*   __restrict__ neighbor_map,  // [IMG*IMG]
    const float*  __restrict__ embeddings,    // [N_PTS, EMB]
    const float*  __restrict__ harmonics,     // [EMB]
    float*        __restrict__ out,           // [N_Q, EMB]
    int n_q)
{
    __shared__ int4   s_nb[WARPS_PER_BLOCK][QUERIES_PER_WARP];
    __shared__ float4 s_w [WARPS_PER_BLOCK][QUERIES_PER_WARP];

    const int warp = threadIdx.x >> 5;
    const int lane = threadIdx.x & 31;
    const int gw   = blockIdx.x * WARPS_PER_BLOCK + warp;  // global warp id

    const int n_tiles = (n_q + QUERIES_PER_WARP - 1) / QUERIES_PER_WARP;

    const int sub = lane >> 3;        // 0..3
    const int fq  = (lane & 7) * 4;   // 0,4,...,28
    const float4 h4 = *(const float4*)&harmonics[fq];

    for (int t = gw; t < n_tiles; t += TOTAL_WARPS) {
        const int qbase = t * QUERIES_PER_WARP;
        const bool full_tile = (qbase + QUERIES_PER_WARP) <= n_q;

        // ---- Phase 1: one query per lane, scalar work done exactly once ----
        {
            const int q = qbase + lane;
            if (full_tile || q < n_q) {
                const float2 p = position[q];
                const int ix = (int)floorf(p.x);
                const int iy = (int)floorf(p.y);
                const int4 nb = neighbor_map[ix * IMG + iy];

                const float2 p0 = positions[nb.x];
                const float2 p1 = positions[nb.y];
                const float2 p2 = positions[nb.z];
                const float2 p3 = positions[nb.w];

                const float fx = (float)ix, fy = (float)iy;
                float dx, dy;
                dx = p0.x - fx; dy = p0.y - fy;
                const float d0 = sqrtf(dx * dx + dy * dy);
                dx = p1.x - fx; dy = p1.y - fy;
                const float d1 = sqrtf(dx * dx + dy * dy);
                dx = p2.x - fx; dy = p2.y - fy;
                const float d2 = sqrtf(dx * dx + dy * dy);
                dx = p3.x - fx; dy = p3.y - fy;
                const float d3 = sqrtf(dx * dx + dy * dy);

                const float rs = 1.0f / (d0 + d1 + d2 + d3 + 1e-8f);
                float4 w;
                w.x = 1.0f - d0 * rs;
                w.y = 1.0f - d1 * rs;
                w.z = 1.0f - d2 * rs;
                w.w = 1.0f - d3 * rs;

                s_nb[warp][lane] = nb;
                s_w [warp][lane] = w;
            }
        }
        __syncwarp();

        // ---- Phase 2: 4 queries per iteration ----
        if (full_tile) {
            #pragma unroll
            for (int i = 0; i < QUERIES_PER_WARP; i += 4) {
                const int4   nb = s_nb[warp][i + sub];  // LDS.128
                const float4 w  = s_w [warp][i + sub];  // LDS.128

                const float4 e0 = __ldg((const float4*)&embeddings[(long)nb.x * EMB + fq]);
                const float4 e1 = __ldg((const float4*)&embeddings[(long)nb.y * EMB + fq]);
                const float4 e2 = __ldg((const float4*)&embeddings[(long)nb.z * EMB + fq]);
                const float4 e3 = __ldg((const float4*)&embeddings[(long)nb.w * EMB + fq]);

                float4 acc;
                acc.x = w.x * e0.x + w.y * e1.x + w.z * e2.x + w.w * e3.x;
                acc.y = w.x * e0.y + w.y * e1.y + w.z * e2.y + w.w * e3.y;
                acc.z = w.x * e0.z + w.y * e1.z + w.z * e2.z + w.w * e3.z;
                acc.w = w.x * e0.w + w.y * e1.w + w.z * e2.w + w.w * e3.w;

                acc.x *= h4.x; acc.y *= h4.y; acc.z *= h4.z; acc.w *= h4.w;

                *(float4*)&out[(long)(qbase + i + sub) * EMB + fq] = acc;
            }
        } else {
            #pragma unroll
            for (int i = 0; i < QUERIES_PER_WARP; i += 4) {
                const int q = qbase + i + sub;
                if (q < n_q) {
                    const int4   nb = s_nb[warp][i + sub];
                    const float4 w  = s_w [warp][i + sub];

                    const float4 e0 = __ldg((const float4*)&embeddings[(long)nb.x * EMB + fq]);
                    const float4 e1 = __ldg((const float4*)&embeddings[(long)nb.y * EMB + fq]);
                    const float4 e2 = __ldg((const float4*)&embeddings[(long)nb.z * EMB + fq]);
                    const float4 e3 = __ldg((const float4*)&embeddings[(long)nb.w * EMB + fq]);

                    float4 acc;
                    acc.x = w.x * e0.x + w.y * e1.x + w.z * e2.x + w.w * e3.x;
                    acc.y = w.x * e0.y + w.y * e1.y + w.z * e2.y + w.w * e3.y;
                    acc.z = w.x * e0.z + w.y * e1.z + w.z * e2.z + w.w * e3.z;
                    acc.w = w.x * e0.w + w.y * e1.w + w.z * e2.w + w.w * e3.w;

                    acc.x *= h4.x; acc.y *= h4.y; acc.z *= h4.z; acc.w *= h4.w;

                    *(float4*)&out[(long)q * EMB + fq] = acc;
                }
            }
        }
        __syncwarp();  // protect smem slice before next tile's phase 1
    }
}

extern "C" void kernel_launch(void* const* d_in, const int* in_sizes, int n_in,
                              void* d_out, int out_size)
{
    const float2* position     = (const float2*)d_in[0];
    const float2* positions    = (const float2*)d_in[1];
    const int4*   neighbor_map = (const int4*)d_in[2];
    const float*  embeddings   = (const float*)d_in[3];
    const float*  harmonics    = (const float*)d_in[4];
    float*        out          = (float*)d_out;

    const int n_q = in_sizes[0] / 2;
    latent_map_kernel<<<BLOCKS, WARPS_PER_BLOCK * 32>>>(
        position, positions, neighbor_map, embeddings, harmonics, out, n_q);
}

// round 16
// speedup vs baseline: 1.8145x; 1.0654x over previous
#include <cuda_runtime.h>
#include <cuda_bf16.h>

// LatentMap — FINAL: warp-cooperative two-phase fused kernel (R4, the
// measured champion at 65.5us).
//
// Phase 1: lane l computes per-query scalars (neighbor indices + normalized
//          inverse-distance weights) for query qbase + l, exactly once, and
//          parks them in smem. (Deduplicates all scalar work 32x vs the
//          naive warp-per-query layout: 189us -> 76us.)
// Phase 2: the warp sweeps its 32 queries 4 at a time; lane -> (query sub =
//          lane>>3, feature quad = (lane&7)*4) via float4: 2 conflict-free
//          LDS.128, 4 perfectly-coalesced LDG.128 embedding gathers (full
//          128B lines), 1 STG.128 spanning 512B contiguous output, ~20 FFMA.
//          (Amortizes instruction count 4x: 76us -> 65.5us.)
//
// Session findings (all measured on sm_100a, ncu-verified): the kernel is
// l1tex wavefront+replay bound at ~74% L1 SOL with ~18.5 SM-cyc/query.
// Neutral or negative: occupancy 43->57 warps/SM, intra-warp MLP doubling,
// scatter/stream kernel split, unroll capping, warp-broadcast gathers,
// streaming stores, 128-thread CTAs, fp16-staged embeddings (main -2.3us,
// convert +3.9us), TMA tile::gather4 (+53us), persistent grid (+4us).
// The 5 scattered wavefronts/query (neighbor_map + 4 positions, random
// indices by construction) are algorithm-intrinsic.

#define IMG 1024
#define EMB 32
#define WARPS_PER_BLOCK 8
#define QUERIES_PER_WARP 32

__global__ void __launch_bounds__(WARPS_PER_BLOCK * 32) latent_map_kernel(
    const float2* __restrict__ position,      // [N_Q]
    const float2* __restrict__ positions,     // [N_PTS]
    const int4*   __restrict__ neighbor_map,  // [IMG*IMG]
    const float*  __restrict__ embeddings,    // [N_PTS, EMB]
    const float*  __restrict__ harmonics,     // [EMB]
    float*        __restrict__ out,           // [N_Q, EMB]
    int n_q)
{
    __shared__ int4   s_nb[WARPS_PER_BLOCK][QUERIES_PER_WARP];
    __shared__ float4 s_w [WARPS_PER_BLOCK][QUERIES_PER_WARP];

    const int warp = threadIdx.x >> 5;
    const int lane = threadIdx.x & 31;
    const int qbase = (blockIdx.x * WARPS_PER_BLOCK + warp) * QUERIES_PER_WARP;

    // ---- Phase 1: one query per lane, scalar work done exactly once ----
    {
        const int q = qbase + lane;
        if (q < n_q) {
            const float2 p = position[q];
            const int ix = (int)floorf(p.x);
            const int iy = (int)floorf(p.y);
            const int4 nb = neighbor_map[ix * IMG + iy];

            const float2 p0 = positions[nb.x];
            const float2 p1 = positions[nb.y];
            const float2 p2 = positions[nb.z];
            const float2 p3 = positions[nb.w];

            const float fx = (float)ix, fy = (float)iy;
            float dx, dy;
            dx = p0.x - fx; dy = p0.y - fy;
            const float d0 = sqrtf(dx * dx + dy * dy);
            dx = p1.x - fx; dy = p1.y - fy;
            const float d1 = sqrtf(dx * dx + dy * dy);
            dx = p2.x - fx; dy = p2.y - fy;
            const float d2 = sqrtf(dx * dx + dy * dy);
            dx = p3.x - fx; dy = p3.y - fy;
            const float d3 = sqrtf(dx * dx + dy * dy);

            const float rs = 1.0f / (d0 + d1 + d2 + d3 + 1e-8f);
            float4 w;
            w.x = 1.0f - d0 * rs;
            w.y = 1.0f - d1 * rs;
            w.z = 1.0f - d2 * rs;
            w.w = 1.0f - d3 * rs;

            s_nb[warp][lane] = nb;
            s_w [warp][lane] = w;
        }
    }
    __syncwarp();

    // ---- Phase 2: 4 queries per iteration; lane -> (query sub, feature quad)
    const int sub = lane >> 3;        // 0..3 : which of the 4 queries
    const int fq  = (lane & 7) * 4;   // feature quad base: 0,4,...,28

    const float4 h4 = *(const float4*)&harmonics[fq];

    #pragma unroll
    for (int i = 0; i < QUERIES_PER_WARP; i += 4) {
        const int q = qbase + i + sub;
        if (q < n_q) {
            const int4   nb = s_nb[warp][i + sub];  // LDS.128, 4 distinct addrs
            const float4 w  = s_w [warp][i + sub];  // LDS.128

            const float4 e0 = *(const float4*)&embeddings[(long)nb.x * EMB + fq];
            const float4 e1 = *(const float4*)&embeddings[(long)nb.y * EMB + fq];
            const float4 e2 = *(const float4*)&embeddings[(long)nb.z * EMB + fq];
            const float4 e3 = *(const float4*)&embeddings[(long)nb.w * EMB + fq];

            float4 acc;
            acc.x = w.x * e0.x + w.y * e1.x + w.z * e2.x + w.w * e3.x;
            acc.y = w.x * e0.y + w.y * e1.y + w.z * e2.y + w.w * e3.y;
            acc.z = w.x * e0.z + w.y * e1.z + w.z * e2.z + w.w * e3.z;
            acc.w = w.x * e0.w + w.y * e1.w + w.z * e2.w + w.w * e3.w;

            acc.x *= h4.x; acc.y *= h4.y; acc.z *= h4.z; acc.w *= h4.w;

            *(float4*)&out[(long)q * EMB + fq] = acc;
        }
    }
}

extern "C" void kernel_launch(void* const* d_in, const int* in_sizes, int n_in,
                              void* d_out, int out_size)
{
    const float2* position     = (const float2*)d_in[0];
    const float2* positions    = (const float2*)d_in[1];
    const int4*   neighbor_map = (const int4*)d_in[2];
    const float*  embeddings   = (const float*)d_in[3];
    const float*  harmonics    = (const float*)d_in[4];
    float*        out          = (float*)d_out;

    const int n_q = in_sizes[0] / 2;
    const int queries_per_block = WARPS_PER_BLOCK * QUERIES_PER_WARP; // 256
    const int grid = (n_q + queries_per_block - 1) / queries_per_block;
    latent_map_kernel<<<grid, WARPS_PER_BLOCK * 32>>>(
        position, positions, neighbor_map, embeddings, harmonics, out, n_q);
}